// round 11
// baseline (speedup 1.0000x reference)
#include <cuda_runtime.h>
#include <cstdint>

// Problem constants (fixed by setup_inputs): B=32, T_src=1024, H=512.
#define B_DIM 32
#define T_SRC 1024
#define H_DIM 512
#define THREADS 256
#define ROWS 16          // output rows per block (two 128-thread row-groups x 8)
#define ROWS_PG 8        // rows per row-group

// SINGLE fused kernel: grid (ceil(max_len/16), B), 256 threads.
// Prologue (amortized over 2x more payload than R10): load this batch's 1024
// durations (4 per thread, L2-resident), inclusive scan into SMEM (sequential-4
// + warp shuffle + 8-warp combine), then 16 threads binary-search the 16 output
// rows' source frames. Body: two 128-thread row-groups each run the R8-proven
// batched path — 8 independent LDG.128 (MLP=8, x L2-resident) then 8 streaming
// STG.128 for the write-once output.
__global__ void __launch_bounds__(THREADS) lr_fused_kernel(
    const float* __restrict__ x,
    const int*  __restrict__ dur,
    float* __restrict__ out,
    float* __restrict__ mask,
    int max_len)
{
    __shared__ int s_cum[T_SRC];
    __shared__ int s_wsum[8];
    __shared__ int s_idx[ROWS];

    const int t0   = blockIdx.x * ROWS;
    const int b    = blockIdx.y;
    const int tid  = threadIdx.x;        // 0..255
    const int lane = tid & 31;
    const int wid  = tid >> 5;           // 0..7

    // ---- Prologue: scan durations[b, :] into s_cum ----
    {
        const int4 d0 = __ldg(reinterpret_cast<const int4*>(dur + b * T_SRC) + tid);
        int p0 = d0.x;
        int p1 = p0 + d0.y;
        int p2 = p1 + d0.z;
        int p3 = p2 + d0.w;

        int sc = p3;  // this thread's total
#pragma unroll
        for (int off = 1; off < 32; off <<= 1) {
            int n = __shfl_up_sync(0xffffffffu, sc, off);
            if (lane >= off) sc += n;
        }
        if (lane == 31) s_wsum[wid] = sc;
        __syncthreads();

        int base = 0;
#pragma unroll
        for (int w = 0; w < 8; ++w) base += (w < wid) ? s_wsum[w] : 0;
        const int tb = base + sc - p3;

        int* c = s_cum + tid * 4;
        c[0] = tb + p0; c[1] = tb + p1; c[2] = tb + p2; c[3] = tb + p3;
    }
    __syncthreads();

    const int total = s_cum[T_SRC - 1];

    // ---- 16 searchsorted lookups (threads 0..15), broadcast via SMEM ----
    if (tid < ROWS) {
        int t = t0 + tid;
        int idx = -1;
        if (t < max_len && t < total) {
            int lo = 0, hi = T_SRC;          // first s with cum[s] > t
            while (lo < hi) {
                int mid = (lo + hi) >> 1;
                if (s_cum[mid] <= t) lo = mid + 1; else hi = mid;
            }
            idx = lo < (T_SRC - 1) ? lo : (T_SRC - 1);
        }
        s_idx[tid] = idx;
    }
    __syncthreads();

    // ---- Body: two row-groups, batched gather (MLP=8) + streaming stores ----
    const int grp  = tid >> 7;           // 0 or 1
    const int gl   = tid & 127;          // lane within row-group
    const int gt0  = t0 + grp * ROWS_PG; // first row of this group

    int idx[ROWS_PG];
#pragma unroll
    for (int r = 0; r < ROWS_PG; ++r) idx[r] = s_idx[grp * ROWS_PG + r];

    const float4* __restrict__ xb =
        reinterpret_cast<const float4*>(x + (size_t)b * T_SRC * H_DIM);
    float4* __restrict__ ob =
        reinterpret_cast<float4*>(out + (size_t)b * max_len * H_DIM);

    float4 v[ROWS_PG];
#pragma unroll
    for (int r = 0; r < ROWS_PG; ++r) {
        v[r] = (idx[r] >= 0)
                 ? __ldg(&xb[(size_t)idx[r] * (H_DIM / 4) + gl])
                 : make_float4(0.f, 0.f, 0.f, 0.f);
    }
#pragma unroll
    for (int r = 0; r < ROWS_PG; ++r) {
        int t = gt0 + r;
        if (t < max_len)
            __stcs(&ob[(size_t)t * (H_DIM / 4) + gl], v[r]);
    }

    // Mask: threads 0..15 write one row each.
    if (tid < ROWS) {
        int t = t0 + tid;
        if (t < max_len)
            mask[(size_t)b * max_len + t] = (t >= total) ? 1.0f : 0.0f;
    }
}

extern "C" void kernel_launch(void* const* d_in, const int* in_sizes, int n_in,
                              void* d_out, int out_size) {
    const float* x   = (const float*)d_in[0];
    const int*   dur = (const int*)d_in[1];
    float* out = (float*)d_out;

    // out_size = B*max_len*H + B*max_len = B*max_len*(H+1)
    const int max_len = out_size / (B_DIM * (H_DIM + 1));
    float* mask = out + (size_t)B_DIM * max_len * H_DIM;

    dim3 grid((max_len + ROWS - 1) / ROWS, B_DIM);
    lr_fused_kernel<<<grid, THREADS>>>(x, dur, out, mask, max_len);
}

// round 12
// speedup vs baseline: 1.3465x; 1.3465x over previous
#include <cuda_runtime.h>
#include <cstdint>

// Problem constants (fixed by setup_inputs): B=32, T_src=1024, H=512.
#define B_DIM 32
#define T_SRC 1024
#define H_DIM 512
#define ROWS 8   // output rows per block

// SINGLE fused kernel: grid (ceil(max_len/8), B), 128 threads.
// R10 configuration — empirical optimum after mapping ROWS {4,8}, batched vs
// pipelined, 128 vs 256 threads. Prologue (hidden by occupancy): load this
// batch's 1024 durations (L2-resident, 2x int4 per thread), inclusive scan
// into SMEM (sequential-8 + warp shuffle + cross-warp combine), then 8
// threads binary-search the 8 output rows' source frames. Body: 8 independent
// LDG.128 (MLP=8, x stays L2-resident) then 8 streaming STG.128 for the
// write-once output.
__global__ void __launch_bounds__(128) lr_fused_kernel(
    const float* __restrict__ x,
    const int*  __restrict__ dur,
    float* __restrict__ out,
    float* __restrict__ mask,
    int max_len)
{
    __shared__ int s_cum[T_SRC];
    __shared__ int s_wsum[4];
    __shared__ int s_idx[ROWS];

    const int t0   = blockIdx.x * ROWS;
    const int b    = blockIdx.y;
    const int tid  = threadIdx.x;        // 0..127
    const int lane = tid & 31;
    const int wid  = tid >> 5;

    // ---- Prologue: scan durations[b, :] into s_cum ----
    {
        const int4* dr = reinterpret_cast<const int4*>(dur + b * T_SRC + tid * 8);
        int4 d0 = __ldg(&dr[0]);
        int4 d1 = __ldg(&dr[1]);
        int e0 = d0.x, e1 = d0.y, e2 = d0.z, e3 = d0.w;
        int e4 = d1.x, e5 = d1.y, e6 = d1.z, e7 = d1.w;

        int p0 = e0, p1 = p0 + e1, p2 = p1 + e2, p3 = p2 + e3;
        int p4 = p3 + e4, p5 = p4 + e5, p6 = p5 + e6, p7 = p6 + e7;

        int sc = p7;  // this thread's total
#pragma unroll
        for (int off = 1; off < 32; off <<= 1) {
            int n = __shfl_up_sync(0xffffffffu, sc, off);
            if (lane >= off) sc += n;
        }
        if (lane == 31) s_wsum[wid] = sc;
        __syncthreads();

        int base = 0;
#pragma unroll
        for (int w = 0; w < 4; ++w) base += (w < wid) ? s_wsum[w] : 0;
        const int tb = base + sc - p7;

        int* c = s_cum + tid * 8;
        c[0] = tb + p0; c[1] = tb + p1; c[2] = tb + p2; c[3] = tb + p3;
        c[4] = tb + p4; c[5] = tb + p5; c[6] = tb + p6; c[7] = tb + p7;
    }
    __syncthreads();

    const int total = s_cum[T_SRC - 1];

    // ---- 8 searchsorted lookups (threads 0..7), results broadcast via SMEM ----
    if (tid < ROWS) {
        int t = t0 + tid;
        int idx = -1;
        if (t < max_len && t < total) {
            int lo = 0, hi = T_SRC;          // first s with cum[s] > t
            while (lo < hi) {
                int mid = (lo + hi) >> 1;
                if (s_cum[mid] <= t) lo = mid + 1; else hi = mid;
            }
            idx = lo < (T_SRC - 1) ? lo : (T_SRC - 1);
        }
        s_idx[tid] = idx;
    }
    __syncthreads();

    // ---- Body: batched gather (MLP=8) + streaming stores ----
    int idx[ROWS];
#pragma unroll
    for (int r = 0; r < ROWS; ++r) idx[r] = s_idx[r];

    const float4* __restrict__ xb =
        reinterpret_cast<const float4*>(x + (size_t)b * T_SRC * H_DIM);
    float4* __restrict__ ob =
        reinterpret_cast<float4*>(out + (size_t)b * max_len * H_DIM);

    float4 v[ROWS];
#pragma unroll
    for (int r = 0; r < ROWS; ++r) {
        v[r] = (idx[r] >= 0)
                 ? __ldg(&xb[(size_t)idx[r] * (H_DIM / 4) + tid])
                 : make_float4(0.f, 0.f, 0.f, 0.f);
    }
#pragma unroll
    for (int r = 0; r < ROWS; ++r) {
        int t = t0 + r;
        if (t < max_len)
            __stcs(&ob[(size_t)t * (H_DIM / 4) + tid], v[r]);
    }

    // Mask: lanes 0..ROWS-1 write one row each.
    if (tid < ROWS) {
        int t = t0 + tid;
        if (t < max_len)
            mask[(size_t)b * max_len + t] = (t >= total) ? 1.0f : 0.0f;
    }
}

extern "C" void kernel_launch(void* const* d_in, const int* in_sizes, int n_in,
                              void* d_out, int out_size) {
    const float* x   = (const float*)d_in[0];
    const int*   dur = (const int*)d_in[1];
    float* out = (float*)d_out;

    // out_size = B*max_len*H + B*max_len = B*max_len*(H+1)
    const int max_len = out_size / (B_DIM * (H_DIM + 1));
    float* mask = out + (size_t)B_DIM * max_len * H_DIM;

    dim3 grid((max_len + ROWS - 1) / ROWS, B_DIM);
    lr_fused_kernel<<<grid, 128>>>(x, dur, out, mask, max_len);
}